// round 2
// baseline (speedup 1.0000x reference)
#include <cuda_runtime.h>
#include <math.h>

// ---------------- problem-size constants (fixed by the dataset) ----------------
#define N_MAX 100000
#define E_MAX 300000
#define V_MAX 50000
#define H_MAX 1152
#define C_MAX 576
#define F_MAX 576

// ---------------- static scratch (no allocation allowed) ----------------
__device__ float g_nodeA[(size_t)N_MAX * H_MAX];            // X @ (W1a - W1b)
__device__ float g_nodeB[(size_t)N_MAX * H_MAX];            // X @ W1b
__device__ float g_edgeH[(size_t)E_MAX * H_MAX];            // per-edge hidden
__device__ float g_edgeO[(size_t)E_MAX * C_MAX];            // per-edge output
__device__ float g_node1[(size_t)N_MAX * C_MAX];            // node features (ping)
__device__ float g_node2[(size_t)N_MAX * C_MAX];            // node features (pong)
__device__ float g_vsum [(size_t)V_MAX * (C_MAX / 3)];      // vertex sums
__device__ float g_Wd   [(size_t)F_MAX * H_MAX];            // W1a - W1b
__device__ float g_invdeg[N_MAX];
__device__ float g_invcnt[V_MAX];
__device__ float g_bnsum[2 * C_MAX];
__device__ float g_bnsc [2 * C_MAX];

// ---------------- kernels ----------------

__global__ void count_kernel(const int* __restrict__ idx, float* __restrict__ cnt, int n) {
    int i = blockIdx.x * blockDim.x + threadIdx.x;
    if (i < n) atomicAdd(&cnt[idx[i]], 1.0f);
}

__global__ void invclip_kernel(float* __restrict__ v, int n) {
    int i = blockIdx.x * blockDim.x + threadIdx.x;
    if (i < n) v[i] = 1.0f / fmaxf(v[i], 1.0f);
}

// NeRF positional embedding: x[N,16] -> out[N,196]
__global__ void embed_kernel(const float* __restrict__ x, float* __restrict__ out, int N) {
    int n = blockIdx.x * blockDim.x + threadIdx.x;
    if (n >= N) return;
    const float* xr = x + (size_t)n * 16;
    float* o = out + (size_t)n * 196;
    int p = 0;
    #pragma unroll
    for (int blk = 0; blk < 3; blk++) {
        const float* pv = xr + blk * 3;
        o[p++] = pv[0]; o[p++] = pv[1]; o[p++] = pv[2];
        #pragma unroll
        for (int c = 0; c < 3; c++) {
            float f = 1.0f;
            #pragma unroll
            for (int k = 0; k < 10; k++) {
                float s, co;
                sincosf(pv[c] * f, &s, &co);
                o[p++] = s; o[p++] = co;
                f *= 2.0f;
            }
        }
    }
    #pragma unroll
    for (int c = 9; c < 16; c++) o[p++] = xr[c];
}

// Wd = W1[0:F] - W1[F:2F]   (both [F,H] row-major, contiguous halves)
__global__ void wdiff_kernel(const float* __restrict__ w1, float* __restrict__ wd, int total) {
    int i = blockIdx.x * blockDim.x + threadIdx.x;
    if (i < total) wd[i] = w1[i] - w1[total + i];
}

// C = A @ B (+bias)(relu), all row-major, fully bounds-checked.
#define GBM 128
#define GBN 128
#define GBK 16
__global__ void __launch_bounds__(256)
gemm_kernel(const float* __restrict__ A, const float* __restrict__ B,
            const float* __restrict__ bias, float* __restrict__ C,
            int M, int K, int Ncols, int relu)
{
    __shared__ float As[GBK][GBM];
    __shared__ float Bs[GBK][GBN];
    int t = threadIdx.x;
    int brow = blockIdx.y * GBM;
    int bcol = blockIdx.x * GBN;
    int tm0 = (t / 16) * 8;
    int tn0 = (t % 16) * 8;

    float acc[8][8];
    #pragma unroll
    for (int i = 0; i < 8; i++)
        #pragma unroll
        for (int j = 0; j < 8; j++) acc[i][j] = 0.0f;

    for (int k0 = 0; k0 < K; k0 += GBK) {
        #pragma unroll
        for (int i = 0; i < 8; i++) {                 // A tile: 128 x 16
            int li = t + i * 256;
            int m  = li >> 4;
            int kk = li & 15;
            int gm = brow + m, gk = k0 + kk;
            As[kk][m] = (gm < M && gk < K) ? A[(size_t)gm * K + gk] : 0.0f;
        }
        #pragma unroll
        for (int i = 0; i < 8; i++) {                 // B tile: 16 x 128
            int li = t + i * 256;
            int kk = li >> 7;
            int n  = li & 127;
            int gk = k0 + kk, gn = bcol + n;
            Bs[kk][n] = (gk < K && gn < Ncols) ? B[(size_t)gk * Ncols + gn] : 0.0f;
        }
        __syncthreads();
        #pragma unroll
        for (int kk = 0; kk < GBK; kk++) {
            float a[8], b[8];
            #pragma unroll
            for (int i = 0; i < 8; i++) a[i] = As[kk][tm0 + i];
            #pragma unroll
            for (int j = 0; j < 8; j++) b[j] = Bs[kk][tn0 + j];
            #pragma unroll
            for (int i = 0; i < 8; i++)
                #pragma unroll
                for (int j = 0; j < 8; j++) acc[i][j] += a[i] * b[j];
        }
        __syncthreads();
    }
    #pragma unroll
    for (int i = 0; i < 8; i++) {
        int gm = brow + tm0 + i;
        if (gm >= M) continue;
        #pragma unroll
        for (int j = 0; j < 8; j++) {
            int gn = bcol + tn0 + j;
            if (gn >= Ncols) continue;
            float v = acc[i][j];
            if (bias) v += bias[gn];
            if (relu) v = fmaxf(v, 0.0f);
            C[(size_t)gm * Ncols + gn] = v;
        }
    }
}

// edgeH[e,:] = relu(A[dst[e],:] + B[src[e],:] + b1)
__global__ void edge_hidden_kernel(const float* __restrict__ A, const float* __restrict__ B,
                                   const float* __restrict__ b1, const int* __restrict__ src,
                                   const int* __restrict__ dst, float* __restrict__ out, int H)
{
    int e = blockIdx.x;
    int s = src[e], d = dst[e];
    const float* ap = A + (size_t)d * H;
    const float* bp = B + (size_t)s * H;
    float* op = out + (size_t)e * H;
    for (int j = threadIdx.x; j < H; j += blockDim.x)
        op[j] = fmaxf(ap[j] + bp[j] + b1[j], 0.0f);
}

// out[idx[r],:] += src[r,:]
__global__ void scatter_add_kernel(const float* __restrict__ src, const int* __restrict__ idx,
                                   float* __restrict__ out, int C)
{
    int r = blockIdx.x;
    int v = idx[r];
    const float* sp = src + (size_t)r * C;
    float* op = out + (size_t)v * C;
    for (int c = threadIdx.x; c < C; c += blockDim.x)
        atomicAdd(&op[c], sp[c]);
}

// x[r,:] *= w[r]
__global__ void scale_rows_kernel(float* __restrict__ x, const float* __restrict__ w,
                                  int total, int C)
{
    int i = blockIdx.x * blockDim.x + threadIdx.x;
    if (i < total) x[i] *= w[i / C];
}

// out[r,:] = vsum[idx[r],:] * invcnt[idx[r]]
__global__ void gather_mean_kernel(const float* __restrict__ vsum, const int* __restrict__ idx,
                                   const float* __restrict__ invcnt, float* __restrict__ out, int C)
{
    int r = blockIdx.x;
    int v = idx[r];
    float s = invcnt[v];
    const float* sp = vsum + (size_t)v * C;
    float* op = out + (size_t)r * C;
    for (int c = threadIdx.x; c < C; c += blockDim.x)
        op[c] = sp[c] * s;
}

__global__ void bn_stats_kernel(const float* __restrict__ x, float* __restrict__ sums,
                                int Nrows, int C)
{
    __shared__ float ssum[C_MAX];
    __shared__ float ssq [C_MAX];
    for (int c = threadIdx.x; c < C; c += blockDim.x) { ssum[c] = 0.0f; ssq[c] = 0.0f; }
    __syncthreads();
    int rpb = (Nrows + gridDim.x - 1) / gridDim.x;
    size_t r0 = (size_t)blockIdx.x * rpb;
    size_t r1 = (size_t)(blockIdx.x + 1) * rpb;
    if (r1 > (size_t)Nrows) r1 = (size_t)Nrows;
    size_t i0 = r0 * C, i1 = (r0 < r1) ? r1 * C : i0;
    for (size_t i = i0 + threadIdx.x; i < i1; i += blockDim.x) {
        float v = x[i];
        int c = (int)(i % C);
        atomicAdd(&ssum[c], v);
        atomicAdd(&ssq[c], v * v);
    }
    __syncthreads();
    for (int c = threadIdx.x; c < C; c += blockDim.x) {
        atomicAdd(&sums[c],     ssum[c]);
        atomicAdd(&sums[C + c], ssq[c]);
    }
}

__global__ void bn_finalize_kernel(const float* __restrict__ sums, const float* __restrict__ gamma,
                                   const float* __restrict__ beta, float* __restrict__ sc,
                                   int Nrows, int C)
{
    int c = threadIdx.x;
    if (c < C) {
        float inv = 1.0f / (float)Nrows;
        float mu = sums[c] * inv;
        float var = fmaxf(sums[C + c] * inv - mu * mu, 0.0f);
        float s = gamma[c] * rsqrtf(var + 1e-5f);
        sc[c] = s;
        sc[C + c] = beta[c] - mu * s;
    }
}

__global__ void bn_apply_relu_kernel(float* __restrict__ x, const float* __restrict__ sc,
                                     int total, int C)
{
    int i = blockIdx.x * blockDim.x + threadIdx.x;
    if (i < total) {
        int c = i % C;
        x[i] = fmaxf(x[i] * sc[c] + sc[C + c], 0.0f);
    }
}

// ---------------- launch ----------------

extern "C" void kernel_launch(void* const* d_in, const int* in_sizes, int n_in,
                              void* d_out, int out_size)
{
    (void)n_in; (void)out_size;
    const float* x     = (const float*)d_in[0];
    const int*   ei    = (const int*)d_in[1];
    const int*   faces = (const int*)d_in[2];
    int N = in_sizes[0] / 16;
    int E = in_sizes[1] / 2;
    const int V = 50000;
    const int* src = ei;
    const int* dst = ei + E;

    float *nodeA, *nodeB, *edgeH, *edgeO, *node1, *node2, *vsum, *Wd, *invdeg, *invcnt, *bnsum, *bnsc;
    cudaGetSymbolAddress((void**)&nodeA,  g_nodeA);
    cudaGetSymbolAddress((void**)&nodeB,  g_nodeB);
    cudaGetSymbolAddress((void**)&edgeH,  g_edgeH);
    cudaGetSymbolAddress((void**)&edgeO,  g_edgeO);
    cudaGetSymbolAddress((void**)&node1,  g_node1);
    cudaGetSymbolAddress((void**)&node2,  g_node2);
    cudaGetSymbolAddress((void**)&vsum,   g_vsum);
    cudaGetSymbolAddress((void**)&Wd,     g_Wd);
    cudaGetSymbolAddress((void**)&invdeg, g_invdeg);
    cudaGetSymbolAddress((void**)&invcnt, g_invcnt);
    cudaGetSymbolAddress((void**)&bnsum,  g_bnsum);
    cudaGetSymbolAddress((void**)&bnsc,   g_bnsc);

    // degree (edges per dst) and vertex counts (faces) — fixed by inputs
    cudaMemsetAsync(invdeg, 0, (size_t)N * sizeof(float));
    count_kernel<<<(E + 255) / 256, 256>>>(dst, invdeg, E);
    invclip_kernel<<<(N + 255) / 256, 256>>>(invdeg, N);
    cudaMemsetAsync(invcnt, 0, (size_t)V * sizeof(float));
    count_kernel<<<(3 * N + 255) / 256, 256>>>(faces, invcnt, 3 * N);
    invclip_kernel<<<(V + 255) / 256, 256>>>(invcnt, V);

    // positional embedding -> node1 [N,196]
    embed_kernel<<<(N + 127) / 128, 128>>>(x, node1, N);

    const int Fd[5] = {196,  96, 192, 384, 384};
    const int Hd[5] = {192, 384, 768, 768, 1152};
    const int Cd[5] = { 96, 192, 384, 384, 576};

    float* cur = node1;
    float* oth = node2;
    for (int l = 0; l < 5; l++) {
        int F = Fd[l], H = Hd[l], C = Cd[l];
        const float* w1 = (const float*)d_in[4 + 4 * l];
        const float* b1 = (const float*)d_in[5 + 4 * l];
        const float* w2 = (const float*)d_in[6 + 4 * l];
        const float* b2 = (const float*)d_in[7 + 4 * l];
        int FH = F * H;

        // EdgeConv via per-node precompute:
        //   hidden_e = relu( (X@(W1a-W1b))[dst] + (X@W1b)[src] + b1 )
        wdiff_kernel<<<(FH + 255) / 256, 256>>>(w1, Wd, FH);
        dim3 gA((H + GBN - 1) / GBN, (N + GBM - 1) / GBM);
        gemm_kernel<<<gA, 256>>>(cur, Wd,      nullptr, nodeA, N, F, H, 0);
        gemm_kernel<<<gA, 256>>>(cur, w1 + FH, nullptr, nodeB, N, F, H, 0);
        edge_hidden_kernel<<<E, 256>>>(nodeA, nodeB, b1, src, dst, edgeH, H);

        dim3 gE((C + GBN - 1) / GBN, (E + GBM - 1) / GBM);
        gemm_kernel<<<gE, 256>>>(edgeH, w2, b2, edgeO, E, H, C, 0);

        // mean-aggregate over dst
        cudaMemsetAsync(oth, 0, (size_t)N * C * sizeof(float));
        scatter_add_kernel<<<E, 128>>>(edgeO, dst, oth, C);
        scale_rows_kernel<<<(N * C + 255) / 256, 256>>>(oth, invdeg, N * C, C);

        if (l < 4) {
            const float* gamma = (const float*)d_in[24 + 2 * l];
            const float* beta  = (const float*)d_in[25 + 2 * l];
            cudaMemsetAsync(bnsum, 0, 2 * C * sizeof(float));
            bn_stats_kernel<<<512, 256>>>(oth, bnsum, N, C);
            bn_finalize_kernel<<<1, C>>>(bnsum, gamma, beta, bnsc, N, C);
            bn_apply_relu_kernel<<<(N * C + 255) / 256, 256>>>(oth, bnsc, N * C, C);
        }

        // distribute_features: [N,C] viewed as [3N, C/3] scattered to V then gathered back
        int C3 = C / 3, R = 3 * N;
        cudaMemsetAsync(vsum, 0, (size_t)V * C3 * sizeof(float));
        scatter_add_kernel<<<R, 128>>>(oth, faces, vsum, C3);
        float* gdst = (l == 4) ? (float*)d_out : oth;
        gather_mean_kernel<<<R, 128>>>(vsum, faces, invcnt, gdst, C3);

        float* t = cur; cur = oth; oth = t;   // gathered result is next layer's input
    }
}

// round 7
// speedup vs baseline: 1.8814x; 1.8814x over previous
#include <cuda_runtime.h>
#include <math.h>

// ---------------- problem-size constants (fixed by the dataset) ----------------
#define N_MAX 100000
#define E_MAX 300000
#define V_MAX 50000
#define H_MAX 1152      // hidden width (2*out)
#define C_MAX 576       // output width
#define F_MAX 384       // max layer input width (except 196 first -> still < 384? no: 196 < 384 ok)

// ---------------- static scratch (no allocation allowed) ----------------
__device__ float g_nodeAB[(size_t)N_MAX * 2 * H_MAX];   // [N, 2H]: cols [0,H)=X@(W1a-W1b), [H,2H)=X@W1b
__device__ float g_aggH [(size_t)N_MAX * H_MAX];        // mean-aggregated edge hidden [N,H]
__device__ float g_node1[(size_t)N_MAX * C_MAX];        // node features (ping)
__device__ float g_node2[(size_t)N_MAX * C_MAX];        // node features (pong)
__device__ float g_vsum [(size_t)V_MAX * (C_MAX / 3)];  // vertex sums
__device__ float g_Wcat [(size_t)F_MAX * 2 * H_MAX];    // [F, 2H] = [W1a-W1b | W1b]
__device__ float g_invdeg[N_MAX];
__device__ float g_degmask[N_MAX];
__device__ float g_invcnt[V_MAX];
__device__ float g_bnsum[2 * C_MAX];
__device__ float g_bnsc [2 * C_MAX];

// ---------------- helpers ----------------
__device__ __forceinline__ void red_add_v4(float* p, float4 v) {
    asm volatile("red.global.add.v4.f32 [%0], {%1,%2,%3,%4};"
                 :: "l"(p), "f"(v.x), "f"(v.y), "f"(v.z), "f"(v.w) : "memory");
}

// ---------------- kernels ----------------

__global__ void count_kernel(const int* __restrict__ idx, float* __restrict__ cnt, int n) {
    int i = blockIdx.x * blockDim.x + threadIdx.x;
    if (i < n) atomicAdd(&cnt[idx[i]], 1.0f);
}

__global__ void invclip_kernel(float* __restrict__ v, int n) {
    int i = blockIdx.x * blockDim.x + threadIdx.x;
    if (i < n) v[i] = 1.0f / fmaxf(v[i], 1.0f);
}

// invdeg = 1/max(cnt,1), mask = (cnt>0)
__global__ void invmask_kernel(float* __restrict__ v, float* __restrict__ mask, int n) {
    int i = blockIdx.x * blockDim.x + threadIdx.x;
    if (i < n) {
        float c = v[i];
        mask[i] = (c > 0.0f) ? 1.0f : 0.0f;
        v[i] = 1.0f / fmaxf(c, 1.0f);
    }
}

// NeRF positional embedding: x[N,16] -> out[N,196]
__global__ void embed_kernel(const float* __restrict__ x, float* __restrict__ out, int N) {
    int n = blockIdx.x * blockDim.x + threadIdx.x;
    if (n >= N) return;
    const float* xr = x + (size_t)n * 16;
    float* o = out + (size_t)n * 196;
    int p = 0;
    #pragma unroll
    for (int blk = 0; blk < 3; blk++) {
        const float* pv = xr + blk * 3;
        o[p++] = pv[0]; o[p++] = pv[1]; o[p++] = pv[2];
        #pragma unroll
        for (int c = 0; c < 3; c++) {
            float f = 1.0f;
            #pragma unroll
            for (int k = 0; k < 10; k++) {
                float s, co;
                sincosf(pv[c] * f, &s, &co);
                o[p++] = s; o[p++] = co;
                f *= 2.0f;
            }
        }
    }
    #pragma unroll
    for (int c = 9; c < 16; c++) o[p++] = xr[c];
}

// Wcat[f, j] = (j<H) ? w1[f,j] - w1[F+f,j] : w1[F+f, j-H]    (w1 is [2F,H] row-major)
__global__ void wcat_kernel(const float* __restrict__ w1, float* __restrict__ wc, int F, int H) {
    int i = blockIdx.x * blockDim.x + threadIdx.x;
    int total = F * 2 * H;
    if (i >= total) return;
    int f = i / (2 * H), j = i - f * 2 * H;
    wc[i] = (j < H) ? (w1[f * H + j] - w1[(F + f) * H + j]) : w1[(F + f) * H + (j - H)];
}

// C = (A @ B) * rowscale[r] + bias * biasmask[r], row-major, bounds-checked.
#define GBM 128
#define GBN 128
#define GBK 16
__global__ void __launch_bounds__(256)
gemm_kernel(const float* __restrict__ A, const float* __restrict__ B,
            const float* __restrict__ bias, const float* __restrict__ rowscale,
            const float* __restrict__ biasmask, float* __restrict__ C,
            int M, int K, int Ncols)
{
    __shared__ float As[GBK][GBM];
    __shared__ float Bs[GBK][GBN];
    int t = threadIdx.x;
    int brow = blockIdx.y * GBM;
    int bcol = blockIdx.x * GBN;
    int tm0 = (t / 16) * 8;
    int tn0 = (t % 16) * 8;

    float acc[8][8];
    #pragma unroll
    for (int i = 0; i < 8; i++)
        #pragma unroll
        for (int j = 0; j < 8; j++) acc[i][j] = 0.0f;

    for (int k0 = 0; k0 < K; k0 += GBK) {
        #pragma unroll
        for (int i = 0; i < 8; i++) {                 // A tile: 128 x 16
            int li = t + i * 256;
            int m  = li >> 4;
            int kk = li & 15;
            int gm = brow + m, gk = k0 + kk;
            As[kk][m] = (gm < M && gk < K) ? A[(size_t)gm * K + gk] : 0.0f;
        }
        #pragma unroll
        for (int i = 0; i < 8; i++) {                 // B tile: 16 x 128
            int li = t + i * 256;
            int kk = li >> 7;
            int n  = li & 127;
            int gk = k0 + kk, gn = bcol + n;
            Bs[kk][n] = (gk < K && gn < Ncols) ? B[(size_t)gk * Ncols + gn] : 0.0f;
        }
        __syncthreads();
        #pragma unroll
        for (int kk = 0; kk < GBK; kk++) {
            float a[8], b[8];
            #pragma unroll
            for (int i = 0; i < 8; i++) a[i] = As[kk][tm0 + i];
            #pragma unroll
            for (int j = 0; j < 8; j++) b[j] = Bs[kk][tn0 + j];
            #pragma unroll
            for (int i = 0; i < 8; i++)
                #pragma unroll
                for (int j = 0; j < 8; j++) acc[i][j] += a[i] * b[j];
        }
        __syncthreads();
    }
    #pragma unroll
    for (int i = 0; i < 8; i++) {
        int gm = brow + tm0 + i;
        if (gm >= M) continue;
        float rs = rowscale ? rowscale[gm] : 1.0f;
        float bm = biasmask ? biasmask[gm] : 1.0f;
        #pragma unroll
        for (int j = 0; j < 8; j++) {
            int gn = bcol + tn0 + j;
            if (gn >= Ncols) continue;
            float v = acc[i][j] * rs;
            if (bias) v += bias[gn] * bm;
            C[(size_t)gm * Ncols + gn] = v;
        }
    }
}

// For each edge e, col-group j: agg[dst[e]] += relu(AB[dst[e],j] + AB[src[e],H+j] + b1[j])
__global__ void edge_agg_kernel(const float* __restrict__ nodeAB, const float* __restrict__ b1,
                                const int* __restrict__ src, const int* __restrict__ dst,
                                float* __restrict__ agg, int H, int H4, int total)
{
    int i = blockIdx.x * blockDim.x + threadIdx.x;
    if (i >= total) return;
    int e = i / H4, j = i - e * H4;
    int s = src[e], d = dst[e];
    size_t H2 = 2 * (size_t)H;
    float4 a = *(const float4*)(nodeAB + (size_t)d * H2 + 4 * j);
    float4 b = *(const float4*)(nodeAB + (size_t)s * H2 + H + 4 * j);
    float4 c = *(const float4*)(b1 + 4 * j);
    float4 v;
    v.x = fmaxf(a.x + b.x + c.x, 0.0f);
    v.y = fmaxf(a.y + b.y + c.y, 0.0f);
    v.z = fmaxf(a.z + b.z + c.z, 0.0f);
    v.w = fmaxf(a.w + b.w + c.w, 0.0f);
    red_add_v4(agg + (size_t)d * H + 4 * j, v);
}

// out[idx[r], c4] += src[r, c4]   (float4 granularity)
__global__ void scatter_rows_kernel(const float* __restrict__ src_, const int* __restrict__ idx,
                                    float* __restrict__ out, int C4, int total)
{
    int i = blockIdx.x * blockDim.x + threadIdx.x;
    if (i >= total) return;
    int r = i / C4, c = i - r * C4;
    int v = idx[r];
    float4 val = ((const float4*)src_)[(size_t)r * C4 + c];
    red_add_v4(out + ((size_t)v * C4 + c) * 4, val);
}

// out[r, c4] = vsum[idx[r], c4] * invcnt[idx[r]]
__global__ void gather_mean_kernel(const float* __restrict__ vsum, const int* __restrict__ idx,
                                   const float* __restrict__ invcnt, float* __restrict__ out,
                                   int C4, int total)
{
    int i = blockIdx.x * blockDim.x + threadIdx.x;
    if (i >= total) return;
    int r = i / C4, c = i - r * C4;
    int v = idx[r];
    float s = invcnt[v];
    float4 val = ((const float4*)vsum)[(size_t)v * C4 + c];
    val.x *= s; val.y *= s; val.z *= s; val.w *= s;
    ((float4*)out)[(size_t)r * C4 + c] = val;
}

__global__ void bn_stats_kernel(const float* __restrict__ x, float* __restrict__ sums,
                                int Nrows, int C)
{
    __shared__ float ssum[C_MAX];
    __shared__ float ssq [C_MAX];
    for (int c = threadIdx.x; c < C; c += blockDim.x) { ssum[c] = 0.0f; ssq[c] = 0.0f; }
    __syncthreads();
    int rpb = (Nrows + gridDim.x - 1) / gridDim.x;
    size_t r0 = (size_t)blockIdx.x * rpb;
    size_t r1 = (size_t)(blockIdx.x + 1) * rpb;
    if (r1 > (size_t)Nrows) r1 = (size_t)Nrows;
    size_t i0 = r0 * C, i1 = (r0 < r1) ? r1 * C : i0;
    for (size_t i = i0 + threadIdx.x; i < i1; i += blockDim.x) {
        float v = x[i];
        int c = (int)(i % C);
        atomicAdd(&ssum[c], v);
        atomicAdd(&ssq[c], v * v);
    }
    __syncthreads();
    for (int c = threadIdx.x; c < C; c += blockDim.x) {
        atomicAdd(&sums[c],     ssum[c]);
        atomicAdd(&sums[C + c], ssq[c]);
    }
}

__global__ void bn_finalize_kernel(const float* __restrict__ sums, const float* __restrict__ gamma,
                                   const float* __restrict__ beta, float* __restrict__ sc,
                                   int Nrows, int C)
{
    int c = threadIdx.x;
    if (c < C) {
        float inv = 1.0f / (float)Nrows;
        float mu = sums[c] * inv;
        float var = fmaxf(sums[C + c] * inv - mu * mu, 0.0f);
        float s = gamma[c] * rsqrtf(var + 1e-5f);
        sc[c] = s;
        sc[C + c] = beta[c] - mu * s;
    }
}

__global__ void bn_apply_relu_kernel(float* __restrict__ x, const float* __restrict__ sc,
                                     int C4, int total)
{
    int i = blockIdx.x * blockDim.x + threadIdx.x;
    if (i >= total) return;
    int c = i % C4;
    float4 v = ((float4*)x)[i];
    float4 s = ((const float4*)sc)[c];
    float4 o = ((const float4*)sc)[C4 + c];
    v.x = fmaxf(v.x * s.x + o.x, 0.0f);
    v.y = fmaxf(v.y * s.y + o.y, 0.0f);
    v.z = fmaxf(v.z * s.z + o.z, 0.0f);
    v.w = fmaxf(v.w * s.w + o.w, 0.0f);
    ((float4*)x)[i] = v;
}

// ---------------- launch ----------------

extern "C" void kernel_launch(void* const* d_in, const int* in_sizes, int n_in,
                              void* d_out, int out_size)
{
    (void)n_in; (void)out_size;
    const float* x     = (const float*)d_in[0];
    const int*   ei    = (const int*)d_in[1];
    const int*   faces = (const int*)d_in[2];
    int N = in_sizes[0] / 16;
    int E = in_sizes[1] / 2;
    const int V = 50000;
    const int* src = ei;
    const int* dst = ei + E;

    float *nodeAB, *aggH, *node1, *node2, *vsum, *Wcat, *invdeg, *degmask, *invcnt, *bnsum, *bnsc;
    cudaGetSymbolAddress((void**)&nodeAB,  g_nodeAB);
    cudaGetSymbolAddress((void**)&aggH,    g_aggH);
    cudaGetSymbolAddress((void**)&node1,   g_node1);
    cudaGetSymbolAddress((void**)&node2,   g_node2);
    cudaGetSymbolAddress((void**)&vsum,    g_vsum);
    cudaGetSymbolAddress((void**)&Wcat,    g_Wcat);
    cudaGetSymbolAddress((void**)&invdeg,  g_invdeg);
    cudaGetSymbolAddress((void**)&degmask, g_degmask);
    cudaGetSymbolAddress((void**)&invcnt,  g_invcnt);
    cudaGetSymbolAddress((void**)&bnsum,   g_bnsum);
    cudaGetSymbolAddress((void**)&bnsc,    g_bnsc);

    // degree (edges per dst) with zero-degree mask; vertex counts (faces)
    cudaMemsetAsync(invdeg, 0, (size_t)N * sizeof(float));
    count_kernel<<<(E + 255) / 256, 256>>>(dst, invdeg, E);
    invmask_kernel<<<(N + 255) / 256, 256>>>(invdeg, degmask, N);
    cudaMemsetAsync(invcnt, 0, (size_t)V * sizeof(float));
    count_kernel<<<(3 * N + 255) / 256, 256>>>(faces, invcnt, 3 * N);
    invclip_kernel<<<(V + 255) / 256, 256>>>(invcnt, V);

    // positional embedding -> node1 [N,196]
    embed_kernel<<<(N + 127) / 128, 128>>>(x, node1, N);

    const int Fd[5] = {196,  96, 192, 384, 384};
    const int Hd[5] = {192, 384, 768, 768, 1152};
    const int Cd[5] = { 96, 192, 384, 384, 576};

    float* cur = node1;
    float* oth = node2;
    for (int l = 0; l < 5; l++) {
        int F = Fd[l], H = Hd[l], C = Cd[l];
        const float* w1 = (const float*)d_in[4 + 4 * l];
        const float* b1 = (const float*)d_in[5 + 4 * l];
        const float* w2 = (const float*)d_in[6 + 4 * l];
        const float* b2 = (const float*)d_in[7 + 4 * l];

        // Wcat = [W1a - W1b | W1b]  -> one GEMM for both node pre-activations
        int FW = F * 2 * H;
        wcat_kernel<<<(FW + 255) / 256, 256>>>(w1, Wcat, F, H);
        dim3 gA((2 * H + GBN - 1) / GBN, (N + GBM - 1) / GBM);
        gemm_kernel<<<gA, 256>>>(cur, Wcat, nullptr, nullptr, nullptr, nodeAB, N, F, 2 * H);

        // aggregate edge hidden directly into [N,H]:
        //   agg[d] += relu(AB[d, 0:H] + AB[s, H:2H] + b1)
        cudaMemsetAsync(aggH, 0, (size_t)N * H * sizeof(float));
        int H4 = H / 4, totE = E * H4;
        edge_agg_kernel<<<(totE + 255) / 256, 256>>>(nodeAB, b1, src, dst, aggH, H, H4, totE);

        // second MLP layer pushed through the mean: oth = (agg*invdeg) @ W2 + b2*mask
        dim3 gB((C + GBN - 1) / GBN, (N + GBM - 1) / GBM);
        gemm_kernel<<<gB, 256>>>(aggH, w2, b2, invdeg, degmask, oth, N, H, C);

        if (l < 4) {
            const float* gamma = (const float*)d_in[24 + 2 * l];
            const float* beta  = (const float*)d_in[25 + 2 * l];
            cudaMemsetAsync(bnsum, 0, 2 * C * sizeof(float));
            bn_stats_kernel<<<512, 256>>>(oth, bnsum, N, C);
            bn_finalize_kernel<<<1, C>>>(bnsum, gamma, beta, bnsc, N, C);
            int tot4 = N * C / 4;
            bn_apply_relu_kernel<<<(tot4 + 255) / 256, 256>>>(oth, bnsc, C / 4, tot4);
        }

        // distribute_features: [N,C] viewed as [3N, C/3] scattered to V then gathered back
        int C3 = C / 3, C34 = C3 / 4, R = 3 * N;
        cudaMemsetAsync(vsum, 0, (size_t)V * C3 * sizeof(float));
        int totS = R * C34;
        scatter_rows_kernel<<<(totS + 255) / 256, 256>>>(oth, faces, vsum, C34, totS);
        float* gdst = (l == 4) ? (float*)d_out : oth;
        gather_mean_kernel<<<(totS + 255) / 256, 256>>>(vsum, faces, invcnt, gdst, C34, totS);

        float* t = cur; cur = oth; oth = t;   // gathered result is next layer's input
    }
}

// round 8
// speedup vs baseline: 2.0800x; 1.1056x over previous
#include <cuda_runtime.h>
#include <math.h>

// ---------------- problem-size constants (fixed by the dataset) ----------------
#define N_MAX 100000
#define E_MAX 300000
#define V_MAX 50000
#define H_MAX 1152      // hidden width (2*out)
#define C_MAX 576       // output width
#define F_MAX 384       // max layer input width

// ---------------- static scratch (no allocation allowed) ----------------
__device__ float g_nodeAB[(size_t)N_MAX * 2 * H_MAX];   // [N, 2H]: cols [0,H)=X@(W1a-W1b), [H,2H)=X@W1b
__device__ float g_aggH [(size_t)N_MAX * H_MAX];        // mean-aggregated edge hidden [N,H]
__device__ float g_node1[(size_t)N_MAX * C_MAX];        // node features (ping)
__device__ float g_node2[(size_t)N_MAX * C_MAX];        // node features (pong)
__device__ float g_vsum [(size_t)V_MAX * (C_MAX / 3)];  // vertex sums
__device__ float g_Wcat [(size_t)F_MAX * 2 * H_MAX];    // [F, 2H] = [W1a-W1b | W1b]
__device__ float g_invdeg[N_MAX];
__device__ float g_degmask[N_MAX];
__device__ float g_invcnt[V_MAX];
__device__ float g_bnsum[2 * C_MAX];
__device__ float g_bnsc [2 * C_MAX];

// ---------------- helpers ----------------
__device__ __forceinline__ void red_add_v4(float* p, float4 v) {
    asm volatile("red.global.add.v4.f32 [%0], {%1,%2,%3,%4};"
                 :: "l"(p), "f"(v.x), "f"(v.y), "f"(v.z), "f"(v.w) : "memory");
}

// packed f32x2 FMA: d = a*b + d (per 32-bit lane)
#define FMA_F32X2(d, a, b) \
    asm("fma.rn.f32x2 %0, %1, %2, %0;" : "+l"(d) : "l"(a), "l"(b))

// duplicate a scalar into both lanes of an f32x2
#define DUP_F32X2(d, s) \
    asm("mov.b64 %0, {%1, %1};" : "=l"(d) : "f"(s))

// unpack f32x2 into two floats
#define UNPACK_F32X2_(lo, hi, v) \
    asm("mov.b64 {%0, %1}, %2;" : "=f"(lo), "=f"(hi) : "l"(v))

// ---------------- kernels ----------------

__global__ void count_kernel(const int* __restrict__ idx, float* __restrict__ cnt, int n) {
    int i = blockIdx.x * blockDim.x + threadIdx.x;
    if (i < n) atomicAdd(&cnt[idx[i]], 1.0f);
}

__global__ void invclip_kernel(float* __restrict__ v, int n) {
    int i = blockIdx.x * blockDim.x + threadIdx.x;
    if (i < n) v[i] = 1.0f / fmaxf(v[i], 1.0f);
}

// invdeg = 1/max(cnt,1), mask = (cnt>0)
__global__ void invmask_kernel(float* __restrict__ v, float* __restrict__ mask, int n) {
    int i = blockIdx.x * blockDim.x + threadIdx.x;
    if (i < n) {
        float c = v[i];
        mask[i] = (c > 0.0f) ? 1.0f : 0.0f;
        v[i] = 1.0f / fmaxf(c, 1.0f);
    }
}

// NeRF positional embedding: x[N,16] -> out[N,196]
__global__ void embed_kernel(const float* __restrict__ x, float* __restrict__ out, int N) {
    int n = blockIdx.x * blockDim.x + threadIdx.x;
    if (n >= N) return;
    const float* xr = x + (size_t)n * 16;
    float* o = out + (size_t)n * 196;
    int p = 0;
    #pragma unroll
    for (int blk = 0; blk < 3; blk++) {
        const float* pv = xr + blk * 3;
        o[p++] = pv[0]; o[p++] = pv[1]; o[p++] = pv[2];
        #pragma unroll
        for (int c = 0; c < 3; c++) {
            float f = 1.0f;
            #pragma unroll
            for (int k = 0; k < 10; k++) {
                float s, co;
                sincosf(pv[c] * f, &s, &co);
                o[p++] = s; o[p++] = co;
                f *= 2.0f;
            }
        }
    }
    #pragma unroll
    for (int c = 9; c < 16; c++) o[p++] = xr[c];
}

// Wcat[f, j] = (j<H) ? w1[f,j] - w1[F+f,j] : w1[F+f, j-H]    (w1 is [2F,H] row-major)
__global__ void wcat_kernel(const float* __restrict__ w1, float* __restrict__ wc, int F, int H) {
    int i = blockIdx.x * blockDim.x + threadIdx.x;
    int total = F * 2 * H;
    if (i >= total) return;
    int f = i / (2 * H), j = i - f * 2 * H;
    wc[i] = (j < H) ? (w1[f * H + j] - w1[(F + f) * H + j]) : w1[(F + f) * H + (j - H)];
}

// C = (A @ B) * rowscale[r] + bias * biasmask[r], row-major, bounds-checked.
// Inner loop uses packed fma.rn.f32x2 (FFMA2) — full-rate fp32 on sm_103a
// (3-reg scalar FFMA is half-rate, rt_SMSP=2).
#define GBM 128
#define GBN 128
#define GBK 16
__global__ void __launch_bounds__(256)
gemm_kernel(const float* __restrict__ A, const float* __restrict__ B,
            const float* __restrict__ bias, const float* __restrict__ rowscale,
            const float* __restrict__ biasmask, float* __restrict__ C,
            int M, int K, int Ncols)
{
    __shared__ float As[2][GBK][GBM];
    __shared__ float Bs[2][GBK][GBN];
    int t = threadIdx.x;
    int brow = blockIdx.y * GBM;
    int bcol = blockIdx.x * GBN;
    // 4+4 split tile: rows {tm0a..+3, tm0b..+3}, cols {tn0a..+3, tn0b..+3}
    int tm0a = (t >> 4) * 4, tm0b = tm0a + 64;
    int tn0a = (t & 15) * 4, tn0b = tn0a + 64;

    // acc[mp][j]: mp 0..1 -> row pairs (tm0a+2mp, +1); mp 2..3 -> (tm0b+2(mp-2), +1)
    // j 0..3 -> cols tn0a+j ; j 4..7 -> cols tn0b+j-4
    unsigned long long acc[4][8];
    #pragma unroll
    for (int mp = 0; mp < 4; mp++)
        #pragma unroll
        for (int j = 0; j < 8; j++) acc[mp][j] = 0ull;   // bit pattern of (0.f, 0.f)

    float pa[8], pb[8];
    int ntiles = (K + GBK - 1) / GBK;

    // prefetch tile 0 into regs, stage to smem buf 0
    #pragma unroll
    for (int i = 0; i < 8; i++) {
        int li = t + i * 256;
        int m = li >> 4, kk = li & 15;
        int gm = brow + m, gk = kk;
        pa[i] = (gm < M && gk < K) ? A[(size_t)gm * K + gk] : 0.0f;
    }
    #pragma unroll
    for (int i = 0; i < 8; i++) {
        int li = t + i * 256;
        int kk = li >> 7, n = li & 127;
        int gk = kk, gn = bcol + n;
        pb[i] = (gk < K && gn < Ncols) ? B[(size_t)gk * Ncols + gn] : 0.0f;
    }
    #pragma unroll
    for (int i = 0; i < 8; i++) {
        int li = t + i * 256;
        As[0][li & 15][li >> 4] = pa[i];
    }
    #pragma unroll
    for (int i = 0; i < 8; i++) {
        int li = t + i * 256;
        Bs[0][li >> 7][li & 127] = pb[i];
    }
    __syncthreads();

    for (int tile = 0; tile < ntiles; tile++) {
        int buf = tile & 1;
        int k0n = (tile + 1) * GBK;
        if (tile + 1 < ntiles) {   // prefetch next tile into regs (hidden behind FFMA2)
            #pragma unroll
            for (int i = 0; i < 8; i++) {
                int li = t + i * 256;
                int m = li >> 4, kk = li & 15;
                int gm = brow + m, gk = k0n + kk;
                pa[i] = (gm < M && gk < K) ? A[(size_t)gm * K + gk] : 0.0f;
            }
            #pragma unroll
            for (int i = 0; i < 8; i++) {
                int li = t + i * 256;
                int kk = li >> 7, n = li & 127;
                int gk = k0n + kk, gn = bcol + n;
                pb[i] = (gk < K && gn < Ncols) ? B[(size_t)gk * Ncols + gn] : 0.0f;
            }
        }
        #pragma unroll
        for (int kk = 0; kk < GBK; kk++) {
            // A pairs load straight into even/odd register pairs (LDS.128)
            ulonglong2 aLo = *reinterpret_cast<const ulonglong2*>(&As[buf][kk][tm0a]);
            ulonglong2 aHi = *reinterpret_cast<const ulonglong2*>(&As[buf][kk][tm0b]);
            unsigned long long ap[4] = {aLo.x, aLo.y, aHi.x, aHi.y};
            float4 bLo = *reinterpret_cast<const float4*>(&Bs[buf][kk][tn0a]);
            float4 bHi = *reinterpret_cast<const float4*>(&Bs[buf][kk][tn0b]);
            unsigned long long bp[8];
            DUP_F32X2(bp[0], bLo.x); DUP_F32X2(bp[1], bLo.y);
            DUP_F32X2(bp[2], bLo.z); DUP_F32X2(bp[3], bLo.w);
            DUP_F32X2(bp[4], bHi.x); DUP_F32X2(bp[5], bHi.y);
            DUP_F32X2(bp[6], bHi.z); DUP_F32X2(bp[7], bHi.w);
            #pragma unroll
            for (int mp = 0; mp < 4; mp++)
                #pragma unroll
                for (int j = 0; j < 8; j++)
                    FMA_F32X2(acc[mp][j], ap[mp], bp[j]);
        }
        if (tile + 1 < ntiles) {
            __syncthreads();
            int nb = buf ^ 1;
            #pragma unroll
            for (int i = 0; i < 8; i++) {
                int li = t + i * 256;
                As[nb][li & 15][li >> 4] = pa[i];
            }
            #pragma unroll
            for (int i = 0; i < 8; i++) {
                int li = t + i * 256;
                Bs[nb][li >> 7][li & 127] = pb[i];
            }
            __syncthreads();
        }
    }

    // epilogue
    #pragma unroll
    for (int mp = 0; mp < 4; mp++) {
        int r0 = (mp < 2) ? (tm0a + 2 * mp) : (tm0b + 2 * (mp - 2));
        int gm0 = brow + r0, gm1 = gm0 + 1;
        bool ok0 = gm0 < M, ok1 = gm1 < M;
        float rs0 = (rowscale && ok0) ? rowscale[gm0] : 1.0f;
        float rs1 = (rowscale && ok1) ? rowscale[gm1] : 1.0f;
        float bm0 = (biasmask && ok0) ? biasmask[gm0] : 1.0f;
        float bm1 = (biasmask && ok1) ? biasmask[gm1] : 1.0f;
        #pragma unroll
        for (int j = 0; j < 8; j++) {
            float lo, hi;
            UNPACK_F32X2_(lo, hi, acc[mp][j]);
            int gn = bcol + ((j < 4) ? (tn0a + j) : (tn0b + j - 4));
            if (gn < Ncols) {
                float bv = bias ? bias[gn] : 0.0f;
                if (ok0) C[(size_t)gm0 * Ncols + gn] = lo * rs0 + bv * bm0;
                if (ok1) C[(size_t)gm1 * Ncols + gn] = hi * rs1 + bv * bm1;
            }
        }
    }
}

// For each edge e, col-group j: agg[dst[e]] += relu(AB[dst[e],j] + AB[src[e],H+j] + b1[j])
__global__ void edge_agg_kernel(const float* __restrict__ nodeAB, const float* __restrict__ b1,
                                const int* __restrict__ src, const int* __restrict__ dst,
                                float* __restrict__ agg, int H, int H4, int total)
{
    int i = blockIdx.x * blockDim.x + threadIdx.x;
    if (i >= total) return;
    int e = i / H4, j = i - e * H4;
    int s = src[e], d = dst[e];
    size_t H2 = 2 * (size_t)H;
    float4 a = *(const float4*)(nodeAB + (size_t)d * H2 + 4 * j);
    float4 b = *(const float4*)(nodeAB + (size_t)s * H2 + H + 4 * j);
    float4 c = *(const float4*)(b1 + 4 * j);
    float4 v;
    v.x = fmaxf(a.x + b.x + c.x, 0.0f);
    v.y = fmaxf(a.y + b.y + c.y, 0.0f);
    v.z = fmaxf(a.z + b.z + c.z, 0.0f);
    v.w = fmaxf(a.w + b.w + c.w, 0.0f);
    red_add_v4(agg + (size_t)d * H + 4 * j, v);
}

// out[idx[r], c4] += src[r, c4]   (float4 granularity)
__global__ void scatter_rows_kernel(const float* __restrict__ src_, const int* __restrict__ idx,
                                    float* __restrict__ out, int C4, int total)
{
    int i = blockIdx.x * blockDim.x + threadIdx.x;
    if (i >= total) return;
    int r = i / C4, c = i - r * C4;
    int v = idx[r];
    float4 val = ((const float4*)src_)[(size_t)r * C4 + c];
    red_add_v4(out + ((size_t)v * C4 + c) * 4, val);
}

// out[r, c4] = vsum[idx[r], c4] * invcnt[idx[r]]
__global__ void gather_mean_kernel(const float* __restrict__ vsum, const int* __restrict__ idx,
                                   const float* __restrict__ invcnt, float* __restrict__ out,
                                   int C4, int total)
{
    int i = blockIdx.x * blockDim.x + threadIdx.x;
    if (i >= total) return;
    int r = i / C4, c = i - r * C4;
    int v = idx[r];
    float s = invcnt[v];
    float4 val = ((const float4*)vsum)[(size_t)v * C4 + c];
    val.x *= s; val.y *= s; val.z *= s; val.w *= s;
    ((float4*)out)[(size_t)r * C4 + c] = val;
}

__global__ void bn_stats_kernel(const float* __restrict__ x, float* __restrict__ sums,
                                int Nrows, int C)
{
    __shared__ float ssum[C_MAX];
    __shared__ float ssq [C_MAX];
    for (int c = threadIdx.x; c < C; c += blockDim.x) { ssum[c] = 0.0f; ssq[c] = 0.0f; }
    __syncthreads();
    int rpb = (Nrows + gridDim.x - 1) / gridDim.x;
    size_t r0 = (size_t)blockIdx.x * rpb;
    size_t r1 = (size_t)(blockIdx.x + 1) * rpb;
    if (r1 > (size_t)Nrows) r1 = (size_t)Nrows;
    size_t i0 = r0 * C, i1 = (r0 < r1) ? r1 * C : i0;
    for (size_t i = i0 + threadIdx.x; i < i1; i += blockDim.x) {
        float v = x[i];
        int c = (int)(i % C);
        atomicAdd(&ssum[c], v);
        atomicAdd(&ssq[c], v * v);
    }
    __syncthreads();
    for (int c = threadIdx.x; c < C; c += blockDim.x) {
        atomicAdd(&sums[c],     ssum[c]);
        atomicAdd(&sums[C + c], ssq[c]);
    }
}

__global__ void bn_finalize_kernel(const float* __restrict__ sums, const float* __restrict__ gamma,
                                   const float* __restrict__ beta, float* __restrict__ sc,
                                   int Nrows, int C)
{
    int c = threadIdx.x;
    if (c < C) {
        float inv = 1.0f / (float)Nrows;
        float mu = sums[c] * inv;
        float var = fmaxf(sums[C + c] * inv - mu * mu, 0.0f);
        float s = gamma[c] * rsqrtf(var + 1e-5f);
        sc[c] = s;
        sc[C + c] = beta[c] - mu * s;
    }
}

__global__ void bn_apply_relu_kernel(float* __restrict__ x, const float* __restrict__ sc,
                                     int C4, int total)
{
    int i = blockIdx.x * blockDim.x + threadIdx.x;
    if (i >= total) return;
    int c = i % C4;
    float4 v = ((float4*)x)[i];
    float4 s = ((const float4*)sc)[c];
    float4 o = ((const float4*)sc)[C4 + c];
    v.x = fmaxf(v.x * s.x + o.x, 0.0f);
    v.y = fmaxf(v.y * s.y + o.y, 0.0f);
    v.z = fmaxf(v.z * s.z + o.z, 0.0f);
    v.w = fmaxf(v.w * s.w + o.w, 0.0f);
    ((float4*)x)[i] = v;
}

// ---------------- launch ----------------

extern "C" void kernel_launch(void* const* d_in, const int* in_sizes, int n_in,
                              void* d_out, int out_size)
{
    (void)n_in; (void)out_size;
    const float* x     = (const float*)d_in[0];
    const int*   ei    = (const int*)d_in[1];
    const int*   faces = (const int*)d_in[2];
    int N = in_sizes[0] / 16;
    int E = in_sizes[1] / 2;
    const int V = 50000;
    const int* src = ei;
    const int* dst = ei + E;

    float *nodeAB, *aggH, *node1, *node2, *vsum, *Wcat, *invdeg, *degmask, *invcnt, *bnsum, *bnsc;
    cudaGetSymbolAddress((void**)&nodeAB,  g_nodeAB);
    cudaGetSymbolAddress((void**)&aggH,    g_aggH);
    cudaGetSymbolAddress((void**)&node1,   g_node1);
    cudaGetSymbolAddress((void**)&node2,   g_node2);
    cudaGetSymbolAddress((void**)&vsum,    g_vsum);
    cudaGetSymbolAddress((void**)&Wcat,    g_Wcat);
    cudaGetSymbolAddress((void**)&invdeg,  g_invdeg);
    cudaGetSymbolAddress((void**)&degmask, g_degmask);
    cudaGetSymbolAddress((void**)&invcnt,  g_invcnt);
    cudaGetSymbolAddress((void**)&bnsum,   g_bnsum);
    cudaGetSymbolAddress((void**)&bnsc,    g_bnsc);

    // degree (edges per dst) with zero-degree mask; vertex counts (faces)
    cudaMemsetAsync(invdeg, 0, (size_t)N * sizeof(float));
    count_kernel<<<(E + 255) / 256, 256>>>(dst, invdeg, E);
    invmask_kernel<<<(N + 255) / 256, 256>>>(invdeg, degmask, N);
    cudaMemsetAsync(invcnt, 0, (size_t)V * sizeof(float));
    count_kernel<<<(3 * N + 255) / 256, 256>>>(faces, invcnt, 3 * N);
    invclip_kernel<<<(V + 255) / 256, 256>>>(invcnt, V);

    // positional embedding -> node1 [N,196]
    embed_kernel<<<(N + 127) / 128, 128>>>(x, node1, N);

    const int Fd[5] = {196,  96, 192, 384, 384};
    const int Hd[5] = {192, 384, 768, 768, 1152};
    const int Cd[5] = { 96, 192, 384, 384, 576};

    float* cur = node1;
    float* oth = node2;
    for (int l = 0; l < 5; l++) {
        int F = Fd[l], H = Hd[l], C = Cd[l];
        const float* w1 = (const float*)d_in[4 + 4 * l];
        const float* b1 = (const float*)d_in[5 + 4 * l];
        const float* w2 = (const float*)d_in[6 + 4 * l];
        const float* b2 = (const float*)d_in[7 + 4 * l];

        // Wcat = [W1a - W1b | W1b]  -> one GEMM for both node pre-activations
        int FW = F * 2 * H;
        wcat_kernel<<<(FW + 255) / 256, 256>>>(w1, Wcat, F, H);
        dim3 gA((2 * H + GBN - 1) / GBN, (N + GBM - 1) / GBM);
        gemm_kernel<<<gA, 256>>>(cur, Wcat, nullptr, nullptr, nullptr, nodeAB, N, F, 2 * H);

        // aggregate edge hidden directly into [N,H]:
        //   agg[d] += relu(AB[d, 0:H] + AB[s, H:2H] + b1)
        cudaMemsetAsync(aggH, 0, (size_t)N * H * sizeof(float));
        int H4 = H / 4, totE = E * H4;
        edge_agg_kernel<<<(totE + 255) / 256, 256>>>(nodeAB, b1, src, dst, aggH, H, H4, totE);

        // second MLP layer pushed through the mean: oth = (agg*invdeg) @ W2 + b2*mask
        dim3 gB((C + GBN - 1) / GBN, (N + GBM - 1) / GBM);
        gemm_kernel<<<gB, 256>>>(aggH, w2, b2, invdeg, degmask, oth, N, H, C);

        if (l < 4) {
            const float* gamma = (const float*)d_in[24 + 2 * l];
            const float* beta  = (const float*)d_in[25 + 2 * l];
            cudaMemsetAsync(bnsum, 0, 2 * C * sizeof(float));
            bn_stats_kernel<<<512, 256>>>(oth, bnsum, N, C);
            bn_finalize_kernel<<<1, C>>>(bnsum, gamma, beta, bnsc, N, C);
            int tot4 = N * C / 4;
            bn_apply_relu_kernel<<<(tot4 + 255) / 256, 256>>>(oth, bnsc, C / 4, tot4);
        }

        // distribute_features: [N,C] viewed as [3N, C/3] scattered to V then gathered back
        int C3 = C / 3, C34 = C3 / 4, R = 3 * N;
        cudaMemsetAsync(vsum, 0, (size_t)V * C3 * sizeof(float));
        int totS = R * C34;
        scatter_rows_kernel<<<(totS + 255) / 256, 256>>>(oth, faces, vsum, C34, totS);
        float* gdst = (l == 4) ? (float*)d_out : oth;
        gather_mean_kernel<<<(totS + 255) / 256, 256>>>(vsum, faces, invcnt, gdst, C34, totS);

        float* t = cur; cur = oth; oth = t;   // gathered result is next layer's input
    }
}

// round 16
// speedup vs baseline: 3.0508x; 1.4667x over previous
#include <cuda_runtime.h>
#include <math.h>
#include <stdint.h>

// ---------------- problem-size constants (fixed by the dataset) ----------------
#define N_MAX 100000
#define E_MAX 300000
#define V_MAX 50000
#define H_MAX 1152      // hidden width (2*out)
#define C_MAX 576       // output width
#define F_MAX 384       // max layer input width

// ---------------- static scratch (no allocation allowed) ----------------
__device__ float g_nodeAB[(size_t)N_MAX * 2 * H_MAX];   // [N, 2H]
__device__ float g_aggH [(size_t)N_MAX * H_MAX];        // mean-aggregated edge hidden [N,H]
__device__ float g_node1[(size_t)N_MAX * C_MAX];
__device__ float g_node2[(size_t)N_MAX * C_MAX];
__device__ float g_vsum [(size_t)V_MAX * (C_MAX / 3)];
__device__ float g_WcatT[(size_t)2 * H_MAX * F_MAX];    // [2H, F] = [W1a-W1b | W1b]^T
__device__ float g_W2T  [(size_t)C_MAX * H_MAX];        // [C, H] = W2^T
__device__ float g_invdeg[N_MAX];
__device__ float g_degmask[N_MAX];
__device__ float g_invcnt[V_MAX];
__device__ float g_bnsum[2 * C_MAX];
__device__ float g_bnsc [2 * C_MAX];

// ---------------- helpers ----------------
__device__ __forceinline__ void red_add_v4(float* p, float4 v) {
    asm volatile("red.global.add.v4.f32 [%0], {%1,%2,%3,%4};"
                 :: "l"(p), "f"(v.x), "f"(v.y), "f"(v.z), "f"(v.w) : "memory");
}
__device__ __forceinline__ uint32_t f2tf(float f) {
    uint32_t u;
    asm("cvt.rna.tf32.f32 %0, %1;" : "=r"(u) : "f"(f));
    return u;
}
// D += A(16x8, row) @ B(8x8, col) in tf32, fp32 accum
__device__ __forceinline__ void mma_tf32(float* d, const uint32_t* a, const uint32_t* b) {
    asm volatile(
        "mma.sync.aligned.m16n8k8.row.col.f32.tf32.tf32.f32 "
        "{%0,%1,%2,%3}, {%4,%5,%6,%7}, {%8,%9}, {%0,%1,%2,%3};"
        : "+f"(d[0]), "+f"(d[1]), "+f"(d[2]), "+f"(d[3])
        : "r"(a[0]), "r"(a[1]), "r"(a[2]), "r"(a[3]), "r"(b[0]), "r"(b[1]));
}

// ---------------- small kernels ----------------

__global__ void count_kernel(const int* __restrict__ idx, float* __restrict__ cnt, int n) {
    int i = blockIdx.x * blockDim.x + threadIdx.x;
    if (i < n) atomicAdd(&cnt[idx[i]], 1.0f);
}

__global__ void invclip_kernel(float* __restrict__ v, int n) {
    int i = blockIdx.x * blockDim.x + threadIdx.x;
    if (i < n) v[i] = 1.0f / fmaxf(v[i], 1.0f);
}

__global__ void invmask_kernel(float* __restrict__ v, float* __restrict__ mask, int n) {
    int i = blockIdx.x * blockDim.x + threadIdx.x;
    if (i < n) {
        float c = v[i];
        mask[i] = (c > 0.0f) ? 1.0f : 0.0f;
        v[i] = 1.0f / fmaxf(c, 1.0f);
    }
}

// NeRF positional embedding: x[N,16] -> out[N,196]
__global__ void embed_kernel(const float* __restrict__ x, float* __restrict__ out, int N) {
    int n = blockIdx.x * blockDim.x + threadIdx.x;
    if (n >= N) return;
    const float* xr = x + (size_t)n * 16;
    float* o = out + (size_t)n * 196;
    int p = 0;
    #pragma unroll
    for (int blk = 0; blk < 3; blk++) {
        const float* pv = xr + blk * 3;
        o[p++] = pv[0]; o[p++] = pv[1]; o[p++] = pv[2];
        #pragma unroll
        for (int c = 0; c < 3; c++) {
            float f = 1.0f;
            #pragma unroll
            for (int k = 0; k < 10; k++) {
                float s, co;
                sincosf(pv[c] * f, &s, &co);
                o[p++] = s; o[p++] = co;
                f *= 2.0f;
            }
        }
    }
    #pragma unroll
    for (int c = 9; c < 16; c++) o[p++] = xr[c];
}

// WcatT[j, f]: j<H -> w1[f,j]-w1[F+f,j]; j>=H -> w1[F+f, j-H].  (w1 is [2F,H] row-major)
__global__ void wcatT_kernel(const float* __restrict__ w1, float* __restrict__ wt, int F, int H) {
    int i = blockIdx.x * blockDim.x + threadIdx.x;
    int total = 2 * H * F;
    if (i >= total) return;
    int j = i / F, f = i - j * F;
    wt[i] = (j < H) ? (w1[f * H + j] - w1[(F + f) * H + j]) : w1[(F + f) * H + (j - H)];
}

// W2T[c, h] = w2[h, c]   (w2 is [H, C] row-major)
__global__ void w2T_kernel(const float* __restrict__ w2, float* __restrict__ wt, int H, int C) {
    int i = blockIdx.x * blockDim.x + threadIdx.x;
    if (i >= C * H) return;
    int c = i / H, h = i - c * H;
    wt[i] = w2[h * C + c];
}

// ---------------- 3xTF32 mma.sync GEMM (fp32-grade precision) ----------------
// C[M,Ncols] = (A[M,K] @ BT[Ncols,K]^T) * rowscale[r] + bias * biasmask[r]
// Each operand split v = hi + lo (hi = tf32(v), lo = tf32(v - hi));
// acc += hi*hi + hi*lo + lo*hi  (lo*lo dropped, ~2^-22).
// Block 128x128, 8 warps (warp tile 32x64), K-chunks of 16.
#define TCM 128
#define TCN 128
#define TCK 16
#define SMST 20   // padded smem row stride (floats) -> conflict-free frags

__global__ void __launch_bounds__(256, 2)
mma_gemm_kernel(const float* __restrict__ A, const float* __restrict__ BT,
                const float* __restrict__ bias, const float* __restrict__ rowscale,
                const float* __restrict__ biasmask, float* __restrict__ C,
                int M, int K, int Ncols)
{
    __shared__ uint32_t AsH[TCM * SMST];
    __shared__ uint32_t AsL[TCM * SMST];
    __shared__ uint32_t BsH[TCN * SMST];
    __shared__ uint32_t BsL[TCN * SMST];
    int t = threadIdx.x;
    int wid = t >> 5, lid = t & 31;
    int g = lid >> 2, tg = lid & 3;
    int m0 = blockIdx.y * TCM, n0 = blockIdx.x * TCN;
    int wm = (wid & 3) * 32;      // warp M offset in tile
    int wn = (wid >> 2) * 64;     // warp N offset in tile

    float acc[2][8][4];
    #pragma unroll
    for (int mt = 0; mt < 2; mt++)
        #pragma unroll
        for (int nt = 0; nt < 8; nt++)
            #pragma unroll
            for (int q = 0; q < 4; q++) acc[mt][nt][q] = 0.0f;

    int nch = (K + TCK - 1) / TCK;
    for (int ch = 0; ch < nch; ch++) {
        int k0 = ch * TCK;
        __syncthreads();
        // A tile: 128 rows x 16 k (2 float4/thread), hi/lo split at store
        #pragma unroll
        for (int i = 0; i < 2; i++) {
            int idx = t + i * 256;
            int row = idx >> 2, c4 = idx & 3;
            int gm = m0 + row, gk = k0 + c4 * 4;       // K % 4 == 0 for all layers
            float4 v = make_float4(0.f, 0.f, 0.f, 0.f);
            if (gm < M && gk < K) v = *(const float4*)(A + (size_t)gm * K + gk);
            uint4 h, l;
            h.x = f2tf(v.x); l.x = f2tf(v.x - __uint_as_float(h.x));
            h.y = f2tf(v.y); l.y = f2tf(v.y - __uint_as_float(h.y));
            h.z = f2tf(v.z); l.z = f2tf(v.z - __uint_as_float(h.z));
            h.w = f2tf(v.w); l.w = f2tf(v.w - __uint_as_float(h.w));
            *(uint4*)&AsH[row * SMST + c4 * 4] = h;
            *(uint4*)&AsL[row * SMST + c4 * 4] = l;
        }
        // B tile: 128 n-rows x 16 k
        #pragma unroll
        for (int i = 0; i < 2; i++) {
            int idx = t + i * 256;
            int row = idx >> 2, c4 = idx & 3;
            int gn = n0 + row, gk = k0 + c4 * 4;
            float4 v = make_float4(0.f, 0.f, 0.f, 0.f);
            if (gn < Ncols && gk < K) v = *(const float4*)(BT + (size_t)gn * K + gk);
            uint4 h, l;
            h.x = f2tf(v.x); l.x = f2tf(v.x - __uint_as_float(h.x));
            h.y = f2tf(v.y); l.y = f2tf(v.y - __uint_as_float(h.y));
            h.z = f2tf(v.z); l.z = f2tf(v.z - __uint_as_float(h.z));
            h.w = f2tf(v.w); l.w = f2tf(v.w - __uint_as_float(h.w));
            *(uint4*)&BsH[row * SMST + c4 * 4] = h;
            *(uint4*)&BsL[row * SMST + c4 * 4] = l;
        }
        __syncthreads();

        #pragma unroll
        for (int k8 = 0; k8 < TCK; k8 += 8) {
            uint32_t aH[2][4], aL[2][4];
            #pragma unroll
            for (int mt = 0; mt < 2; mt++) {
                int r = wm + 16 * mt + g;
                aH[mt][0] = AsH[r * SMST + k8 + tg];
                aH[mt][1] = AsH[(r + 8) * SMST + k8 + tg];
                aH[mt][2] = AsH[r * SMST + k8 + tg + 4];
                aH[mt][3] = AsH[(r + 8) * SMST + k8 + tg + 4];
                aL[mt][0] = AsL[r * SMST + k8 + tg];
                aL[mt][1] = AsL[(r + 8) * SMST + k8 + tg];
                aL[mt][2] = AsL[r * SMST + k8 + tg + 4];
                aL[mt][3] = AsL[(r + 8) * SMST + k8 + tg + 4];
            }
            // process N in two 32-wide halves to bound register pressure
            #pragma unroll
            for (int nh = 0; nh < 2; nh++) {
                uint32_t bH[4][2], bL[4][2];
                #pragma unroll
                for (int nt = 0; nt < 4; nt++) {
                    int r = wn + 32 * nh + 8 * nt + g;
                    bH[nt][0] = BsH[r * SMST + k8 + tg];
                    bH[nt][1] = BsH[r * SMST + k8 + tg + 4];
                    bL[nt][0] = BsL[r * SMST + k8 + tg];
                    bL[nt][1] = BsL[r * SMST + k8 + tg + 4];
                }
                #pragma unroll
                for (int mt = 0; mt < 2; mt++)
                    #pragma unroll
                    for (int nt = 0; nt < 4; nt++) {
                        float* d = acc[mt][nh * 4 + nt];
                        mma_tf32(d, aH[mt], bH[nt]);   // hi*hi
                        mma_tf32(d, aH[mt], bL[nt]);   // hi*lo
                        mma_tf32(d, aL[mt], bH[nt]);   // lo*hi
                    }
            }
        }
    }

    // epilogue: d0/d1 -> (row, col), (row, col+1); d2/d3 -> (row+8, ...)
    #pragma unroll
    for (int mt = 0; mt < 2; mt++) {
        int r0 = m0 + wm + 16 * mt + g;
        int r1 = r0 + 8;
        bool ok0 = r0 < M, ok1 = r1 < M;
        float rs0 = (rowscale && ok0) ? rowscale[r0] : 1.0f;
        float rs1 = (rowscale && ok1) ? rowscale[r1] : 1.0f;
        float bm0 = (biasmask && ok0) ? biasmask[r0] : 1.0f;
        float bm1 = (biasmask && ok1) ? biasmask[r1] : 1.0f;
        #pragma unroll
        for (int nt = 0; nt < 8; nt++) {
            int col = n0 + wn + 8 * nt + 2 * tg;
            if (col >= Ncols) continue;     // Ncols even -> col+1 valid when col valid
            float b0 = 0.f, b1 = 0.f;
            if (bias) { b0 = bias[col]; b1 = bias[col + 1]; }
            if (ok0) {
                float2 v = make_float2(acc[mt][nt][0] * rs0 + b0 * bm0,
                                       acc[mt][nt][1] * rs0 + b1 * bm0);
                *(float2*)(C + (size_t)r0 * Ncols + col) = v;
            }
            if (ok1) {
                float2 v = make_float2(acc[mt][nt][2] * rs1 + b0 * bm1,
                                       acc[mt][nt][3] * rs1 + b1 * bm1);
                *(float2*)(C + (size_t)r1 * Ncols + col) = v;
            }
        }
    }
}

// ---------------- edge / scatter / bn kernels ----------------

__global__ void edge_agg_kernel(const float* __restrict__ nodeAB, const float* __restrict__ b1,
                                const int* __restrict__ src, const int* __restrict__ dst,
                                float* __restrict__ agg, int H, int H4, int total)
{
    int i = blockIdx.x * blockDim.x + threadIdx.x;
    if (i >= total) return;
    int e = i / H4, j = i - e * H4;
    int s = src[e], d = dst[e];
    size_t H2 = 2 * (size_t)H;
    float4 a = *(const float4*)(nodeAB + (size_t)d * H2 + 4 * j);
    float4 b = *(const float4*)(nodeAB + (size_t)s * H2 + H + 4 * j);
    float4 c = *(const float4*)(b1 + 4 * j);
    float4 v;
    v.x = fmaxf(a.x + b.x + c.x, 0.0f);
    v.y = fmaxf(a.y + b.y + c.y, 0.0f);
    v.z = fmaxf(a.z + b.z + c.z, 0.0f);
    v.w = fmaxf(a.w + b.w + c.w, 0.0f);
    red_add_v4(agg + (size_t)d * H + 4 * j, v);
}

__global__ void scatter_rows_kernel(const float* __restrict__ src_, const int* __restrict__ idx,
                                    float* __restrict__ out, int C4, int total)
{
    int i = blockIdx.x * blockDim.x + threadIdx.x;
    if (i >= total) return;
    int r = i / C4, c = i - r * C4;
    int v = idx[r];
    float4 val = ((const float4*)src_)[(size_t)r * C4 + c];
    red_add_v4(out + ((size_t)v * C4 + c) * 4, val);
}

__global__ void gather_mean_kernel(const float* __restrict__ vsum, const int* __restrict__ idx,
                                   const float* __restrict__ invcnt, float* __restrict__ out,
                                   int C4, int total)
{
    int i = blockIdx.x * blockDim.x + threadIdx.x;
    if (i >= total) return;
    int r = i / C4, c = i - r * C4;
    int v = idx[r];
    float s = invcnt[v];
    float4 val = ((const float4*)vsum)[(size_t)v * C4 + c];
    val.x *= s; val.y *= s; val.z *= s; val.w *= s;
    ((float4*)out)[(size_t)r * C4 + c] = val;
}

__global__ void bn_stats_kernel(const float* __restrict__ x, float* __restrict__ sums,
                                int Nrows, int C)
{
    __shared__ float ssum[C_MAX];
    __shared__ float ssq [C_MAX];
    for (int c = threadIdx.x; c < C; c += blockDim.x) { ssum[c] = 0.0f; ssq[c] = 0.0f; }
    __syncthreads();
    int rpb = (Nrows + gridDim.x - 1) / gridDim.x;
    size_t r0 = (size_t)blockIdx.x * rpb;
    size_t r1 = (size_t)(blockIdx.x + 1) * rpb;
    if (r1 > (size_t)Nrows) r1 = (size_t)Nrows;
    size_t i0 = r0 * C, i1 = (r0 < r1) ? r1 * C : i0;
    for (size_t i = i0 + threadIdx.x; i < i1; i += blockDim.x) {
        float v = x[i];
        int c = (int)(i % C);
        atomicAdd(&ssum[c], v);
        atomicAdd(&ssq[c], v * v);
    }
    __syncthreads();
    for (int c = threadIdx.x; c < C; c += blockDim.x) {
        atomicAdd(&sums[c],     ssum[c]);
        atomicAdd(&sums[C + c], ssq[c]);
    }
}

__global__ void bn_finalize_kernel(const float* __restrict__ sums, const float* __restrict__ gamma,
                                   const float* __restrict__ beta, float* __restrict__ sc,
                                   int Nrows, int C)
{
    int c = threadIdx.x;
    if (c < C) {
        float inv = 1.0f / (float)Nrows;
        float mu = sums[c] * inv;
        float var = fmaxf(sums[C + c] * inv - mu * mu, 0.0f);
        float s = gamma[c] * rsqrtf(var + 1e-5f);
        sc[c] = s;
        sc[C + c] = beta[c] - mu * s;
    }
}

__global__ void bn_apply_relu_kernel(float* __restrict__ x, const float* __restrict__ sc,
                                     int C4, int total)
{
    int i = blockIdx.x * blockDim.x + threadIdx.x;
    if (i >= total) return;
    int c = i % C4;
    float4 v = ((float4*)x)[i];
    float4 s = ((const float4*)sc)[c];
    float4 o = ((const float4*)sc)[C4 + c];
    v.x = fmaxf(v.x * s.x + o.x, 0.0f);
    v.y = fmaxf(v.y * s.y + o.y, 0.0f);
    v.z = fmaxf(v.z * s.z + o.z, 0.0f);
    v.w = fmaxf(v.w * s.w + o.w, 0.0f);
    ((float4*)x)[i] = v;
}

// ---------------- launch ----------------

static void tc_gemm(const float* A, const float* BT, const float* bias,
                    const float* rowscale, const float* biasmask, float* C,
                    int M, int K, int Ncols)
{
    dim3 grid((Ncols + TCN - 1) / TCN, (M + TCM - 1) / TCM);
    mma_gemm_kernel<<<grid, 256>>>(A, BT, bias, rowscale, biasmask, C, M, K, Ncols);
}

extern "C" void kernel_launch(void* const* d_in, const int* in_sizes, int n_in,
                              void* d_out, int out_size)
{
    (void)n_in; (void)out_size;
    const float* x     = (const float*)d_in[0];
    const int*   ei    = (const int*)d_in[1];
    const int*   faces = (const int*)d_in[2];
    int N = in_sizes[0] / 16;
    int E = in_sizes[1] / 2;
    const int V = 50000;
    const int* src = ei;
    const int* dst = ei + E;

    float *nodeAB, *aggH, *node1, *node2, *vsum, *WcatT, *W2T, *invdeg, *degmask, *invcnt, *bnsum, *bnsc;
    cudaGetSymbolAddress((void**)&nodeAB,  g_nodeAB);
    cudaGetSymbolAddress((void**)&aggH,    g_aggH);
    cudaGetSymbolAddress((void**)&node1,   g_node1);
    cudaGetSymbolAddress((void**)&node2,   g_node2);
    cudaGetSymbolAddress((void**)&vsum,    g_vsum);
    cudaGetSymbolAddress((void**)&WcatT,   g_WcatT);
    cudaGetSymbolAddress((void**)&W2T,     g_W2T);
    cudaGetSymbolAddress((void**)&invdeg,  g_invdeg);
    cudaGetSymbolAddress((void**)&degmask, g_degmask);
    cudaGetSymbolAddress((void**)&invcnt,  g_invcnt);
    cudaGetSymbolAddress((void**)&bnsum,   g_bnsum);
    cudaGetSymbolAddress((void**)&bnsc,    g_bnsc);

    const int Fd[5] = {196,  96, 192, 384, 384};
    const int Hd[5] = {192, 384, 768, 768, 1152};
    const int Cd[5] = { 96, 192, 384, 384, 576};

    // Launch order places GEMM1 of layer 1 at launch #6 (ncu -s 5 -c 1 target):
    // 1 embed, 2 memset(invdeg), 3 count(dst), 4 invmask, 5 wcatT, 6 GEMM1.
    embed_kernel<<<(N + 127) / 128, 128>>>(x, node1, N);                       // 1
    cudaMemsetAsync(invdeg, 0, (size_t)N * sizeof(float));                     // 2
    count_kernel<<<(E + 255) / 256, 256>>>(dst, invdeg, E);                    // 3
    invmask_kernel<<<(N + 255) / 256, 256>>>(invdeg, degmask, N);              // 4

    float* cur = node1;
    float* oth = node2;
    for (int l = 0; l < 5; l++) {
        int F = Fd[l], H = Hd[l], C = Cd[l];
        const float* w1 = (const float*)d_in[4 + 4 * l];
        const float* b1 = (const float*)d_in[5 + 4 * l];
        const float* w2 = (const float*)d_in[6 + 4 * l];
        const float* b2 = (const float*)d_in[7 + 4 * l];

        // GEMM1: nodeAB[N, 2H] = cur @ [W1a-W1b | W1b]
        int TW = 2 * H * F;
        wcatT_kernel<<<(TW + 255) / 256, 256>>>(w1, WcatT, F, H);              // 5 (l=0)
        tc_gemm(cur, WcatT, nullptr, nullptr, nullptr, nodeAB, N, F, 2 * H);   // 6 (l=0)

        if (l == 0) {   // face counts — needed first at the distribute below
            cudaMemsetAsync(invcnt, 0, (size_t)V * sizeof(float));
            count_kernel<<<(3 * N + 255) / 256, 256>>>(faces, invcnt, 3 * N);
            invclip_kernel<<<(V + 255) / 256, 256>>>(invcnt, V);
        }

        // aggregate edge hidden: agg[d] += relu(AB[d,0:H] + AB[s,H:2H] + b1)
        cudaMemsetAsync(aggH, 0, (size_t)N * H * sizeof(float));
        int H4 = H / 4, totE = E * H4;
        edge_agg_kernel<<<(totE + 255) / 256, 256>>>(nodeAB, b1, src, dst, aggH, H, H4, totE);

        // GEMM2 (mean pushed through): oth = (agg*invdeg) @ W2 + b2*mask
        w2T_kernel<<<(C * H + 255) / 256, 256>>>(w2, W2T, H, C);
        tc_gemm(aggH, W2T, b2, invdeg, degmask, oth, N, H, C);

        if (l < 4) {
            const float* gamma = (const float*)d_in[24 + 2 * l];
            const float* beta  = (const float*)d_in[25 + 2 * l];
            cudaMemsetAsync(bnsum, 0, 2 * C * sizeof(float));
            bn_stats_kernel<<<512, 256>>>(oth, bnsum, N, C);
            bn_finalize_kernel<<<1, C>>>(bnsum, gamma, beta, bnsc, N, C);
            int tot4 = N * C / 4;
            bn_apply_relu_kernel<<<(tot4 + 255) / 256, 256>>>(oth, bnsc, C / 4, tot4);
        }

        // distribute_features: [N,C] -> [3N, C/3] scatter to V, gather back
        int C3 = C / 3, C34 = C3 / 4, R = 3 * N;
        cudaMemsetAsync(vsum, 0, (size_t)V * C3 * sizeof(float));
        int totS = R * C34;
        scatter_rows_kernel<<<(totS + 255) / 256, 256>>>(oth, faces, vsum, C34, totS);
        float* gdst = (l == 4) ? (float*)d_out : oth;
        gather_mean_kernel<<<(totS + 255) / 256, 256>>>(vsum, faces, invcnt, gdst, C34, totS);

        float* t = cur; cur = oth; oth = t;
    }
}